// round 8
// baseline (speedup 1.0000x reference)
#include <cuda_runtime.h>
#include <cuda_fp16.h>
#include <cstdint>

// ---------------------------------------------------------------------------
// FFT mura metric, v5 (resubmit — R7 was an infra failure, kernel never ran):
//  - rows pass: float4 image loads -> shared gray staging (union'd with FFT
//    exchange buffer), packed real-pair 512-pt FFTs, Hermitian half-spectrum
//    (k <= 256) stored as fp16 (17 MB scratch)
//  - cols pass: 512-pt complex FFT per k, magnitudes, interior k weighted x2
//  - 512-pt FFT = 3x radix-8; exchange1 via shared (pitch 72), exchange2 via
//    8x8 register shuffle transpose; twiddles via __sincosf + chained cmul.
// ---------------------------------------------------------------------------

#define NTHR      256
#define REG_PITCH 580     // float2 per FFT-group region (bank-staggered)

__device__ __half2 g_scratch[32u * 257u * 512u];   // [b][k=0..256][r], complex as half2
__device__ float   g_plow[32 * 65];
__device__ float   g_ptot[32 * 65];

struct alignas(8) H2X2 { __half2 e, o; };

__device__ __forceinline__ float2 cadd(float2 a, float2 b){ return make_float2(a.x+b.x, a.y+b.y); }
__device__ __forceinline__ float2 csub(float2 a, float2 b){ return make_float2(a.x-b.x, a.y-b.y); }
__device__ __forceinline__ float2 cmul(float2 a, float2 b){
    return make_float2(a.x*b.x - a.y*b.y, a.x*b.y + a.y*b.x);
}
__device__ __forceinline__ float2 mnegi(float2 a){ return make_float2( a.y, -a.x); } // * (-i)
__device__ __forceinline__ float2 mposi(float2 a){ return make_float2(-a.y,  a.x); } // * (+i)

__device__ __forceinline__ float fsqrt_approx(float x){
    float r; asm("sqrt.approx.f32 %0, %1;" : "=f"(r) : "f"(x)); return r;
}

// 8-point DFT, natural order: v[m'] = sum_m v_in[m] * w8^(m*m'), w8 = e^{-i pi/4}
__device__ __forceinline__ void dft8(float2* v){
    const float C = 0.70710678118654752440f;
    float2 t0 = cadd(v[0], v[4]);
    float2 t1 = csub(v[0], v[4]);
    float2 t2 = cadd(v[2], v[6]);
    float2 t3 = csub(v[2], v[6]);
    float2 E0 = cadd(t0, t2), E2 = csub(t0, t2);
    float2 E1 = cadd(t1, mnegi(t3));
    float2 E3 = cadd(t1, mposi(t3));
    float2 s0 = cadd(v[1], v[5]);
    float2 s1 = csub(v[1], v[5]);
    float2 s2 = cadd(v[3], v[7]);
    float2 s3 = csub(v[3], v[7]);
    float2 O0 = cadd(s0, s2), O2 = csub(s0, s2);
    float2 O1 = cadd(s1, mnegi(s3));
    float2 O3 = cadd(s1, mposi(s3));
    float2 w1O1 = make_float2(C*(O1.x + O1.y), C*(O1.y - O1.x));
    float2 w2O2 = mnegi(O2);
    float2 w3O3 = make_float2(C*(O3.y - O3.x), -C*(O3.x + O3.y));
    v[0] = cadd(E0, O0);   v[4] = csub(E0, O0);
    v[1] = cadd(E1, w1O1); v[5] = csub(E1, w1O1);
    v[2] = cadd(E2, w2O2); v[6] = csub(E2, w2O2);
    v[3] = cadd(E3, w3O3); v[7] = csub(E3, w3O3);
}

__device__ __forceinline__ float2 shflx(float2 v, int d){
    v.x = __shfl_xor_sync(0xffffffffu, v.x, d);
    v.y = __shfl_xor_sync(0xffffffffu, v.y, d);
    return v;
}

// 8x8 transpose across 8 consecutive lanes (i = lane&7): out a[j] = in a_laneJ[i]
__device__ __forceinline__ void transpose8(float2 a[8], int i){
    #pragma unroll
    for (int d = 1; d < 8; d <<= 1){
        #pragma unroll
        for (int r = 0; r < 8; r++){
            if (r & d) continue;
            const int mate = r | d;
            float2 send = (i & d) ? a[r] : a[mate];
            float2 recv = shflx(send, d);
            if (i & d) a[r] = recv; else a[mate] = recv;
        }
    }
}

// Cooperative 512-pt FFT by 64 threads (n = 0..63) sharing srow.
// Input : a[m] = x[n + 64*m]
// Output: a[t1] = X[(n>>3) + 8*(n&7) + 64*t1]
// Contains one __syncthreads(); all 256 block threads must call together.
// srow is "busy" until the caller syncs after return.
__device__ __forceinline__ void fft512(float2 a[8], float2* srow, int n){
    const int mp = n >> 3, i = n & 7;

    dft8(a);
    float sn, cn;
    __sincosf((float)n * (-6.28318530717958647693f / 512.0f), &sn, &cn);
    {
        float2 base = make_float2(cn, sn);
        float2 w = base;
        #pragma unroll
        for (int m = 1; m < 8; m++){
            a[m] = cmul(a[m], w);
            if (m < 7) w = cmul(w, base);
        }
    }
    #pragma unroll
    for (int m = 0; m < 8; m++) srow[m * 72 + n] = a[m];
    __syncthreads();
    #pragma unroll
    for (int s = 0; s < 8; s++) a[s] = srow[mp * 72 + i + 8 * s];

    dft8(a);
    float s2, c2;
    __sincosf((float)i * (-6.28318530717958647693f / 64.0f), &s2, &c2);
    {
        float2 base = make_float2(c2, s2);
        float2 w = base;
        #pragma unroll
        for (int t = 1; t < 8; t++){
            a[t] = cmul(a[t], w);
            if (t < 7) w = cmul(w, base);
        }
    }
    transpose8(a, i);
    dft8(a);
}

// Kernel 1: gray (float4 loads, smem staging) + packed row-pair FFT +
// Hermitian unpack + fp16 transposed store.
// Grid: 32 images * 64 row-groups; each block: 4 row-pairs (8 rows).
__global__ void __launch_bounds__(NTHR) fft_rows_kernel(const float* __restrict__ img){
    __shared__ union {
        float2 g2[4][512];            // staging: [pair][col] = (gray_even, gray_odd)
        float2 fft[4 * REG_PITCH];    // FFT exchange / k-stage buffer
    } sb;
    const int tid = threadIdx.x;
    const int b   = blockIdx.x >> 6;
    const int g   = blockIdx.x & 63;      // row group: rows g*8 .. g*8+7

    // ---- Phase 0: vectorized gray staging (8 rows x 512 cols) ----
    {
        const float* base = img + (size_t)b * 786432u + (size_t)(g * 8) * 512u;
        #pragma unroll
        for (int j = 0; j < 4; j++){
            int f    = tid + 256 * j;       // float4 index: 0..1023
            int row  = f >> 7;              // 0..7
            int col4 = f & 127;             // float4 within row
            const float4* p0 = reinterpret_cast<const float4*>(base + (size_t)row * 512u) + col4;
            float4 c0 = p0[0];
            float4 c1 = p0[262144 / 4];
            float4 c2 = p0[524288 / 4];
            float4 gr = make_float4((c0.x + c1.x + c2.x) * (1.0f/3.0f),
                                    (c0.y + c1.y + c2.y) * (1.0f/3.0f),
                                    (c0.z + c1.z + c2.z) * (1.0f/3.0f),
                                    (c0.w + c1.w + c2.w) * (1.0f/3.0f));
            int pair = row >> 1, eo = row & 1;
            float* dst = &sb.g2[pair][col4 * 4].x + eo;   // .x for even row, .y for odd
            dst[0] = gr.x; dst[2] = gr.y; dst[4] = gr.z; dst[6] = gr.w;
        }
    }
    __syncthreads();

    const int rr = tid >> 6;              // pair index 0..3
    const int n  = tid & 63;

    float2 a[8];
    #pragma unroll
    for (int m = 0; m < 8; m++) a[m] = sb.g2[rr][n + 64 * m];   // z = even + i*odd
    __syncthreads();                       // all g2 reads done before fft clobbers it

    float2* srow = sb.fft + rr * REG_PITCH;
    fft512(a, srow, n);
    __syncthreads();                       // exchange-1 loads done before restage

    // stage Z in natural k order, pad every 8 to stagger banks
    {
        const int kb = (n >> 3) + 8 * (n & 7);
        #pragma unroll
        for (int t1 = 0; t1 < 8; t1++){
            int k = kb + 64 * t1;
            srow[k + (k >> 3)] = a[t1];
        }
    }
    __syncthreads();

    // Hermitian unpack: lane = 4*kk + p ; each lane emits (Xe,Xo) for (k, pair p)
    const int w  = tid >> 5, l = tid & 31;
    const int kk = l >> 2,  p = l & 3;
    const float2* shp = sb.fft + p * REG_PITCH;
    #pragma unroll
    for (int it = 0; it < 5; it++){
        int  k   = it * 64 + w * 8 + kk;
        bool act = true;
        if (it == 4){ k = 256; act = (w == 0 && kk == 0); }
        if (act){
            int km = (512 - k) & 511;
            float2 zk = shp[k  + (k  >> 3)];
            float2 zm = shp[km + (km >> 3)];
            float2 Xe = make_float2(0.5f * (zk.x + zm.x), 0.5f * (zk.y - zm.y));
            float2 Xo = make_float2(0.5f * (zk.y + zm.y), 0.5f * (zm.x - zk.x));
            size_t off = ((size_t)(b * 257 + k) << 9) + (size_t)(g * 8 + 2 * p);
            H2X2 val;
            val.e = __float22half2_rn(Xe);
            val.o = __float22half2_rn(Xo);
            *reinterpret_cast<H2X2*>(&g_scratch[off]) = val;
        }
    }
}

// Kernel 2: column FFT for k = 0..256, masked magnitude sums (interior k x2)
__global__ void __launch_bounds__(NTHR) fft_cols_kernel(void){
    __shared__ float2 sbuf[4 * REG_PITCH];
    __shared__ float redL[8], redT[8];
    const int tid = threadIdx.x;
    const int b   = blockIdx.x / 65;
    const int kg  = blockIdx.x % 65;
    const int rr  = tid >> 6;
    const int n   = tid & 63;
    const int krow  = kg * 4 + rr;
    const bool valid = (krow < 257);

    const __half2* src = g_scratch + ((size_t)(b * 257 + (valid ? krow : 0)) << 9);
    float2 a[8];
    #pragma unroll
    for (int m = 0; m < 8; m++){
        __half2 h = __ldcs(src + n + 64 * m);
        float2 v = __half22float2(h);
        a[m] = valid ? v : make_float2(0.0f, 0.0f);
    }

    fft512(a, sbuf + rr * REG_PITCH, n);

    // a[t1] = F[u][krow], u = (n>>3) + 8*(n&7) + 64*t1
    const int ub = (n >> 3) + 8 * (n & 7);
    float wgt = !valid ? 0.0f : ((krow == 0 || krow == 256) ? 1.0f : 2.0f);
    float dx  = (float)(krow - 256);
    float dx2 = dx * dx;
    float L = 0.0f, T = 0.0f;
    #pragma unroll
    for (int t1 = 0; t1 < 8; t1++){
        int u = ub + 64 * t1;
        float2 v = a[t1];
        float mag = fsqrt_approx(v.x * v.x + v.y * v.y);
        T += mag;
        float dy = (float)(u - 256);
        if (dy * dy + dx2 <= 2621.44f) L += mag;   // (512*0.1)^2
    }
    L *= wgt; T *= wgt;

    #pragma unroll
    for (int o = 16; o; o >>= 1){
        L += __shfl_down_sync(0xffffffffu, L, o);
        T += __shfl_down_sync(0xffffffffu, T, o);
    }
    const int wid = tid >> 5, lane = tid & 31;
    if (lane == 0){ redL[wid] = L; redT[wid] = T; }
    __syncthreads();
    if (tid == 0){
        float sl = 0.0f, st = 0.0f;
        #pragma unroll
        for (int q = 0; q < 8; q++){ sl += redL[q]; st += redT[q]; }
        g_plow[blockIdx.x] = sl;
        g_ptot[blockIdx.x] = st;
    }
}

// Kernel 3: deterministic final reduction -> scalar
__global__ void __launch_bounds__(1024) finalize_kernel(float* __restrict__ out){
    const int t = threadIdx.x;
    const int b = t >> 5, lane = t & 31;
    float L = 0.0f, T = 0.0f;
    for (int i = lane; i < 65; i += 32){
        L += g_plow[b * 65 + i];
        T += g_ptot[b * 65 + i];
    }
    #pragma unroll
    for (int o = 16; o; o >>= 1){
        L += __shfl_down_sync(0xffffffffu, L, o);
        T += __shfl_down_sync(0xffffffffu, T, o);
    }
    __shared__ float s[32];
    if (lane == 0) s[b] = L / T;
    __syncthreads();
    if (t < 32){
        float v = s[t];
        #pragma unroll
        for (int o = 16; o; o >>= 1) v += __shfl_down_sync(0xffffffffu, v, o);
        if (t == 0) out[0] = v * (1.0f / 32.0f);
    }
}

extern "C" void kernel_launch(void* const* d_in, const int* in_sizes, int n_in,
                              void* d_out, int out_size){
    const float* img = (const float*)d_in[0];
    float* out = (float*)d_out;
    (void)in_sizes; (void)n_in; (void)out_size;

    fft_rows_kernel<<<32 * 64, NTHR>>>(img);
    fft_cols_kernel<<<32 * 65, NTHR>>>();
    finalize_kernel<<<1, 1024>>>(out);
}

// round 11
// speedup vs baseline: 1.0118x; 1.0118x over previous
#include <cuda_runtime.h>
#include <cuda_fp16.h>
#include <cstdint>

// ---------------------------------------------------------------------------
// FFT mura metric, v6:
//  - rows pass: v3-style scalar gray loads (measured best), packed real-pair
//    512-pt FFTs, Hermitian half-spectrum (k <= 256) stored fp16 (17 MB)
//  - cols pass: vectorized 128-bit scratch loads + pitch-9 shared pre-exchange
//    to the FFT's n+64m order; magnitudes, interior k weighted x2
//  - 512-pt FFT = 3x radix-8; exchange1 via shared (pitch 72), exchange2 via
//    8x8 register shuffle transpose; twiddles via __sincosf + chained cmul.
// ---------------------------------------------------------------------------

#define NTHR      256
#define REG_PITCH 580     // float2 per FFT-group region (>= 576 for pre-exchange)

__device__ __half2 g_scratch[32u * 257u * 512u];   // [b][k=0..256][r], complex as half2
__device__ float   g_plow[32 * 65];
__device__ float   g_ptot[32 * 65];

struct alignas(8) H2X2 { __half2 e, o; };

__device__ __forceinline__ float2 cadd(float2 a, float2 b){ return make_float2(a.x+b.x, a.y+b.y); }
__device__ __forceinline__ float2 csub(float2 a, float2 b){ return make_float2(a.x-b.x, a.y-b.y); }
__device__ __forceinline__ float2 cmul(float2 a, float2 b){
    return make_float2(a.x*b.x - a.y*b.y, a.x*b.y + a.y*b.x);
}
__device__ __forceinline__ float2 mnegi(float2 a){ return make_float2( a.y, -a.x); } // * (-i)
__device__ __forceinline__ float2 mposi(float2 a){ return make_float2(-a.y,  a.x); } // * (+i)

__device__ __forceinline__ float fsqrt_approx(float x){
    float r; asm("sqrt.approx.f32 %0, %1;" : "=f"(r) : "f"(x)); return r;
}

// 8-point DFT, natural order: v[m'] = sum_m v_in[m] * w8^(m*m'), w8 = e^{-i pi/4}
__device__ __forceinline__ void dft8(float2* v){
    const float C = 0.70710678118654752440f;
    float2 t0 = cadd(v[0], v[4]);
    float2 t1 = csub(v[0], v[4]);
    float2 t2 = cadd(v[2], v[6]);
    float2 t3 = csub(v[2], v[6]);
    float2 E0 = cadd(t0, t2), E2 = csub(t0, t2);
    float2 E1 = cadd(t1, mnegi(t3));
    float2 E3 = cadd(t1, mposi(t3));
    float2 s0 = cadd(v[1], v[5]);
    float2 s1 = csub(v[1], v[5]);
    float2 s2 = cadd(v[3], v[7]);
    float2 s3 = csub(v[3], v[7]);
    float2 O0 = cadd(s0, s2), O2 = csub(s0, s2);
    float2 O1 = cadd(s1, mnegi(s3));
    float2 O3 = cadd(s1, mposi(s3));
    float2 w1O1 = make_float2(C*(O1.x + O1.y), C*(O1.y - O1.x));
    float2 w2O2 = mnegi(O2);
    float2 w3O3 = make_float2(C*(O3.y - O3.x), -C*(O3.x + O3.y));
    v[0] = cadd(E0, O0);   v[4] = csub(E0, O0);
    v[1] = cadd(E1, w1O1); v[5] = csub(E1, w1O1);
    v[2] = cadd(E2, w2O2); v[6] = csub(E2, w2O2);
    v[3] = cadd(E3, w3O3); v[7] = csub(E3, w3O3);
}

__device__ __forceinline__ float2 shflx(float2 v, int d){
    v.x = __shfl_xor_sync(0xffffffffu, v.x, d);
    v.y = __shfl_xor_sync(0xffffffffu, v.y, d);
    return v;
}

// 8x8 transpose across 8 consecutive lanes (i = lane&7): out a[j] = in a_laneJ[i]
__device__ __forceinline__ void transpose8(float2 a[8], int i){
    #pragma unroll
    for (int d = 1; d < 8; d <<= 1){
        #pragma unroll
        for (int r = 0; r < 8; r++){
            if (r & d) continue;
            const int mate = r | d;
            float2 send = (i & d) ? a[r] : a[mate];
            float2 recv = shflx(send, d);
            if (i & d) a[r] = recv; else a[mate] = recv;
        }
    }
}

// Cooperative 512-pt FFT by 64 threads (n = 0..63) sharing srow.
// Input : a[m] = x[n + 64*m]
// Output: a[t1] = X[(n>>3) + 8*(n&7) + 64*t1]
// Contains one __syncthreads(); all 256 block threads must call together.
// srow is "busy" until the caller syncs after return.
__device__ __forceinline__ void fft512(float2 a[8], float2* srow, int n){
    const int mp = n >> 3, i = n & 7;

    dft8(a);
    float sn, cn;
    __sincosf((float)n * (-6.28318530717958647693f / 512.0f), &sn, &cn);
    {
        float2 base = make_float2(cn, sn);
        float2 w = base;
        #pragma unroll
        for (int m = 1; m < 8; m++){
            a[m] = cmul(a[m], w);
            if (m < 7) w = cmul(w, base);
        }
    }
    #pragma unroll
    for (int m = 0; m < 8; m++) srow[m * 72 + n] = a[m];
    __syncthreads();
    #pragma unroll
    for (int s = 0; s < 8; s++) a[s] = srow[mp * 72 + i + 8 * s];

    dft8(a);
    float s2, c2;
    __sincosf((float)i * (-6.28318530717958647693f / 64.0f), &s2, &c2);
    {
        float2 base = make_float2(c2, s2);
        float2 w = base;
        #pragma unroll
        for (int t = 1; t < 8; t++){
            a[t] = cmul(a[t], w);
            if (t < 7) w = cmul(w, base);
        }
    }
    transpose8(a, i);
    dft8(a);
}

// Kernel 1: gray + packed row-pair FFT + Hermitian unpack + fp16 transposed store
// Grid: 32 images * 64 row-groups; each block: 4 row-pairs (8 rows).
__global__ void __launch_bounds__(NTHR) fft_rows_kernel(const float* __restrict__ img){
    __shared__ float2 sbuf[4 * REG_PITCH];
    const int tid = threadIdx.x;
    const int b   = blockIdx.x >> 6;
    const int g   = blockIdx.x & 63;      // row group: rows g*8 .. g*8+7
    const int rr  = tid >> 6;             // pair index 0..3
    const int n   = tid & 63;

    const int row_e = g * 8 + rr * 2;
    const float* pe = img + (size_t)b * 786432u + (size_t)row_e * 512u;
    const float* po = pe + 512;

    float2 a[8];
    #pragma unroll
    for (int m = 0; m < 8; m++){
        int c = n + 64 * m;
        float ge = (pe[c] + pe[262144 + c] + pe[524288 + c]) * (1.0f / 3.0f);
        float go = (po[c] + po[262144 + c] + po[524288 + c]) * (1.0f / 3.0f);
        a[m] = make_float2(ge, go);       // z = even + i*odd
    }

    float2* srow = sbuf + rr * REG_PITCH;
    fft512(a, srow, n);
    __syncthreads();                       // exchange-1 loads done before restage

    // stage Z in natural k order, pad every 8 to stagger banks
    {
        const int kb = (n >> 3) + 8 * (n & 7);
        #pragma unroll
        for (int t1 = 0; t1 < 8; t1++){
            int k = kb + 64 * t1;
            srow[k + (k >> 3)] = a[t1];
        }
    }
    __syncthreads();

    // Hermitian unpack: lane = 4*kk + p ; each lane emits (Xe,Xo) for (k, pair p)
    const int w  = tid >> 5, l = tid & 31;
    const int kk = l >> 2,  p = l & 3;
    const float2* shp = sbuf + p * REG_PITCH;
    #pragma unroll
    for (int it = 0; it < 5; it++){
        int  k   = it * 64 + w * 8 + kk;
        bool act = true;
        if (it == 4){ k = 256; act = (w == 0 && kk == 0); }
        if (act){
            int km = (512 - k) & 511;
            float2 zk = shp[k  + (k  >> 3)];
            float2 zm = shp[km + (km >> 3)];
            float2 Xe = make_float2(0.5f * (zk.x + zm.x), 0.5f * (zk.y - zm.y));
            float2 Xo = make_float2(0.5f * (zk.y + zm.y), 0.5f * (zm.x - zk.x));
            size_t off = ((size_t)(b * 257 + k) << 9) + (size_t)(g * 8 + 2 * p);
            H2X2 val;
            val.e = __float22half2_rn(Xe);
            val.o = __float22half2_rn(Xo);
            *reinterpret_cast<H2X2*>(&g_scratch[off]) = val;
        }
    }
}

// Kernel 2: column FFT for k = 0..256, masked magnitude sums (interior k x2)
// Scratch reads: 2x LDG.128 per thread (elements 8n..8n+7), then a pitch-9
// shared pre-exchange redistributes to the FFT's n+64m order.
__global__ void __launch_bounds__(NTHR) fft_cols_kernel(void){
    __shared__ float2 sbuf[4 * REG_PITCH];
    __shared__ float redL[8], redT[8];
    const int tid = threadIdx.x;
    const int b   = blockIdx.x / 65;
    const int kg  = blockIdx.x % 65;
    const int rr  = tid >> 6;
    const int n   = tid & 63;
    const int krow  = kg * 4 + rr;
    const bool valid = (krow < 257);

    float2* srow = sbuf + rr * REG_PITCH;

    // ---- vector load: elements r = 8n .. 8n+7 as 2x uint4 ----
    {
        const uint4* src4 = reinterpret_cast<const uint4*>(
            g_scratch + ((size_t)(b * 257 + (valid ? krow : 0)) << 9));
        uint4 v0 = src4[2 * n];
        uint4 v1 = src4[2 * n + 1];
        if (!valid){
            v0 = make_uint4(0u, 0u, 0u, 0u);
            v1 = make_uint4(0u, 0u, 0u, 0u);
        }
        // store to pre-exchange layout: element e = 8q + j -> srow[9q + j]
        float2* dst = srow + 9 * n;
        dst[0] = __half22float2(*reinterpret_cast<__half2*>(&v0.x));
        dst[1] = __half22float2(*reinterpret_cast<__half2*>(&v0.y));
        dst[2] = __half22float2(*reinterpret_cast<__half2*>(&v0.z));
        dst[3] = __half22float2(*reinterpret_cast<__half2*>(&v0.w));
        dst[4] = __half22float2(*reinterpret_cast<__half2*>(&v1.x));
        dst[5] = __half22float2(*reinterpret_cast<__half2*>(&v1.y));
        dst[6] = __half22float2(*reinterpret_cast<__half2*>(&v1.z));
        dst[7] = __half22float2(*reinterpret_cast<__half2*>(&v1.w));
    }
    __syncthreads();

    // gather FFT input order: e = n + 64m -> srow[72m + 9*(n>>3) + (n&7)]
    float2 a[8];
    {
        const float2* gsrc = srow + 9 * (n >> 3) + (n & 7);
        #pragma unroll
        for (int m = 0; m < 8; m++) a[m] = gsrc[72 * m];
    }
    __syncthreads();   // pre-exchange reads done before fft512 writes srow

    fft512(a, srow, n);

    // a[t1] = F[u][krow], u = (n>>3) + 8*(n&7) + 64*t1
    const int ub = (n >> 3) + 8 * (n & 7);
    float wgt = !valid ? 0.0f : ((krow == 0 || krow == 256) ? 1.0f : 2.0f);
    float dx  = (float)(krow - 256);
    float dx2 = dx * dx;
    float L = 0.0f, T = 0.0f;
    #pragma unroll
    for (int t1 = 0; t1 < 8; t1++){
        int u = ub + 64 * t1;
        float2 v = a[t1];
        float mag = fsqrt_approx(v.x * v.x + v.y * v.y);
        T += mag;
        float dy = (float)(u - 256);
        if (dy * dy + dx2 <= 2621.44f) L += mag;   // (512*0.1)^2
    }
    L *= wgt; T *= wgt;

    #pragma unroll
    for (int o = 16; o; o >>= 1){
        L += __shfl_down_sync(0xffffffffu, L, o);
        T += __shfl_down_sync(0xffffffffu, T, o);
    }
    const int wid = tid >> 5, lane = tid & 31;
    if (lane == 0){ redL[wid] = L; redT[wid] = T; }
    __syncthreads();
    if (tid == 0){
        float sl = 0.0f, st = 0.0f;
        #pragma unroll
        for (int q = 0; q < 8; q++){ sl += redL[q]; st += redT[q]; }
        g_plow[blockIdx.x] = sl;
        g_ptot[blockIdx.x] = st;
    }
}

// Kernel 3: deterministic final reduction -> scalar
__global__ void __launch_bounds__(1024) finalize_kernel(float* __restrict__ out){
    const int t = threadIdx.x;
    const int b = t >> 5, lane = t & 31;
    float L = 0.0f, T = 0.0f;
    for (int i = lane; i < 65; i += 32){
        L += g_plow[b * 65 + i];
        T += g_ptot[b * 65 + i];
    }
    #pragma unroll
    for (int o = 16; o; o >>= 1){
        L += __shfl_down_sync(0xffffffffu, L, o);
        T += __shfl_down_sync(0xffffffffu, T, o);
    }
    __shared__ float s[32];
    if (lane == 0) s[b] = L / T;
    __syncthreads();
    if (t < 32){
        float v = s[t];
        #pragma unroll
        for (int o = 16; o; o >>= 1) v += __shfl_down_sync(0xffffffffu, v, o);
        if (t == 0) out[0] = v * (1.0f / 32.0f);
    }
}

extern "C" void kernel_launch(void* const* d_in, const int* in_sizes, int n_in,
                              void* d_out, int out_size){
    const float* img = (const float*)d_in[0];
    float* out = (float*)d_out;
    (void)in_sizes; (void)n_in; (void)out_size;

    fft_rows_kernel<<<32 * 64, NTHR>>>(img);
    fft_cols_kernel<<<32 * 65, NTHR>>>();
    finalize_kernel<<<1, 1024>>>(out);
}

// round 16
// speedup vs baseline: 1.0186x; 1.0067x over previous
#include <cuda_runtime.h>
#include <cuda_fp16.h>
#include <cstdint>

// ---------------------------------------------------------------------------
// FFT mura metric, v7 (resubmit — R14 was an infra failure, kernel never ran):
//  - rows pass (measured-best v6 form): scalar gray loads, packed real-pair
//    512-pt FFTs, Hermitian half-spectrum (k <= 256) stored fp16 (17 MB)
//  - cols pass (measured-best v4 form): direct scalar __ldcs scratch loads,
//    512-pt complex FFT per k, magnitudes, interior k weighted x2
//  - finalize FUSED into cols via last-block reduction (int-counter atomic,
//    deterministic), counter self-resets for graph replay
//  - 512-pt FFT = 3x radix-8; exchange1 via shared (pitch 72), exchange2 via
//    8x8 register shuffle transpose; twiddles via __sincosf + chained cmul.
// ---------------------------------------------------------------------------

#define NTHR      256
#define REG_PITCH 580     // float2 per FFT-group region

__device__ __half2       g_scratch[32u * 257u * 512u];   // [b][k=0..256][r]
__device__ float         g_plow[32 * 65];
__device__ float         g_ptot[32 * 65];
__device__ unsigned int  g_count = 0;

struct alignas(8) H2X2 { __half2 e, o; };

__device__ __forceinline__ float2 cadd(float2 a, float2 b){ return make_float2(a.x+b.x, a.y+b.y); }
__device__ __forceinline__ float2 csub(float2 a, float2 b){ return make_float2(a.x-b.x, a.y-b.y); }
__device__ __forceinline__ float2 cmul(float2 a, float2 b){
    return make_float2(a.x*b.x - a.y*b.y, a.x*b.y + a.y*b.x);
}
__device__ __forceinline__ float2 mnegi(float2 a){ return make_float2( a.y, -a.x); } // * (-i)
__device__ __forceinline__ float2 mposi(float2 a){ return make_float2(-a.y,  a.x); } // * (+i)

__device__ __forceinline__ float fsqrt_approx(float x){
    float r; asm("sqrt.approx.f32 %0, %1;" : "=f"(r) : "f"(x)); return r;
}

// 8-point DFT, natural order: v[m'] = sum_m v_in[m] * w8^(m*m'), w8 = e^{-i pi/4}
__device__ __forceinline__ void dft8(float2* v){
    const float C = 0.70710678118654752440f;
    float2 t0 = cadd(v[0], v[4]);
    float2 t1 = csub(v[0], v[4]);
    float2 t2 = cadd(v[2], v[6]);
    float2 t3 = csub(v[2], v[6]);
    float2 E0 = cadd(t0, t2), E2 = csub(t0, t2);
    float2 E1 = cadd(t1, mnegi(t3));
    float2 E3 = cadd(t1, mposi(t3));
    float2 s0 = cadd(v[1], v[5]);
    float2 s1 = csub(v[1], v[5]);
    float2 s2 = cadd(v[3], v[7]);
    float2 s3 = csub(v[3], v[7]);
    float2 O0 = cadd(s0, s2), O2 = csub(s0, s2);
    float2 O1 = cadd(s1, mnegi(s3));
    float2 O3 = cadd(s1, mposi(s3));
    float2 w1O1 = make_float2(C*(O1.x + O1.y), C*(O1.y - O1.x));
    float2 w2O2 = mnegi(O2);
    float2 w3O3 = make_float2(C*(O3.y - O3.x), -C*(O3.x + O3.y));
    v[0] = cadd(E0, O0);   v[4] = csub(E0, O0);
    v[1] = cadd(E1, w1O1); v[5] = csub(E1, w1O1);
    v[2] = cadd(E2, w2O2); v[6] = csub(E2, w2O2);
    v[3] = cadd(E3, w3O3); v[7] = csub(E3, w3O3);
}

__device__ __forceinline__ float2 shflx(float2 v, int d){
    v.x = __shfl_xor_sync(0xffffffffu, v.x, d);
    v.y = __shfl_xor_sync(0xffffffffu, v.y, d);
    return v;
}

// 8x8 transpose across 8 consecutive lanes (i = lane&7): out a[j] = in a_laneJ[i]
__device__ __forceinline__ void transpose8(float2 a[8], int i){
    #pragma unroll
    for (int d = 1; d < 8; d <<= 1){
        #pragma unroll
        for (int r = 0; r < 8; r++){
            if (r & d) continue;
            const int mate = r | d;
            float2 send = (i & d) ? a[r] : a[mate];
            float2 recv = shflx(send, d);
            if (i & d) a[r] = recv; else a[mate] = recv;
        }
    }
}

// Cooperative 512-pt FFT by 64 threads (n = 0..63) sharing srow.
// Input : a[m] = x[n + 64*m]
// Output: a[t1] = X[(n>>3) + 8*(n&7) + 64*t1]
// Contains one __syncthreads(); all 256 block threads must call together.
// srow is "busy" until the caller syncs after return.
__device__ __forceinline__ void fft512(float2 a[8], float2* srow, int n){
    const int mp = n >> 3, i = n & 7;

    dft8(a);
    float sn, cn;
    __sincosf((float)n * (-6.28318530717958647693f / 512.0f), &sn, &cn);
    {
        float2 base = make_float2(cn, sn);
        float2 w = base;
        #pragma unroll
        for (int m = 1; m < 8; m++){
            a[m] = cmul(a[m], w);
            if (m < 7) w = cmul(w, base);
        }
    }
    #pragma unroll
    for (int m = 0; m < 8; m++) srow[m * 72 + n] = a[m];
    __syncthreads();
    #pragma unroll
    for (int s = 0; s < 8; s++) a[s] = srow[mp * 72 + i + 8 * s];

    dft8(a);
    float s2, c2;
    __sincosf((float)i * (-6.28318530717958647693f / 64.0f), &s2, &c2);
    {
        float2 base = make_float2(c2, s2);
        float2 w = base;
        #pragma unroll
        for (int t = 1; t < 8; t++){
            a[t] = cmul(a[t], w);
            if (t < 7) w = cmul(w, base);
        }
    }
    transpose8(a, i);
    dft8(a);
}

// Kernel 1: gray + packed row-pair FFT + Hermitian unpack + fp16 transposed store
// Grid: 32 images * 64 row-groups; each block: 4 row-pairs (8 rows).
__global__ void __launch_bounds__(NTHR) fft_rows_kernel(const float* __restrict__ img){
    __shared__ float2 sbuf[4 * REG_PITCH];
    const int tid = threadIdx.x;
    const int b   = blockIdx.x >> 6;
    const int g   = blockIdx.x & 63;      // row group: rows g*8 .. g*8+7
    const int rr  = tid >> 6;             // pair index 0..3
    const int n   = tid & 63;

    const int row_e = g * 8 + rr * 2;
    const float* pe = img + (size_t)b * 786432u + (size_t)row_e * 512u;
    const float* po = pe + 512;

    float2 a[8];
    #pragma unroll
    for (int m = 0; m < 8; m++){
        int c = n + 64 * m;
        float ge = (pe[c] + pe[262144 + c] + pe[524288 + c]) * (1.0f / 3.0f);
        float go = (po[c] + po[262144 + c] + po[524288 + c]) * (1.0f / 3.0f);
        a[m] = make_float2(ge, go);       // z = even + i*odd
    }

    float2* srow = sbuf + rr * REG_PITCH;
    fft512(a, srow, n);
    __syncthreads();                       // exchange-1 loads done before restage

    // stage Z in natural k order, pad every 8 to stagger banks
    {
        const int kb = (n >> 3) + 8 * (n & 7);
        #pragma unroll
        for (int t1 = 0; t1 < 8; t1++){
            int k = kb + 64 * t1;
            srow[k + (k >> 3)] = a[t1];
        }
    }
    __syncthreads();

    // Hermitian unpack: lane = 4*kk + p ; each lane emits (Xe,Xo) for (k, pair p)
    const int w  = tid >> 5, l = tid & 31;
    const int kk = l >> 2,  p = l & 3;
    const float2* shp = sbuf + p * REG_PITCH;
    #pragma unroll
    for (int it = 0; it < 5; it++){
        int  k   = it * 64 + w * 8 + kk;
        bool act = true;
        if (it == 4){ k = 256; act = (w == 0 && kk == 0); }
        if (act){
            int km = (512 - k) & 511;
            float2 zk = shp[k  + (k  >> 3)];
            float2 zm = shp[km + (km >> 3)];
            float2 Xe = make_float2(0.5f * (zk.x + zm.x), 0.5f * (zk.y - zm.y));
            float2 Xo = make_float2(0.5f * (zk.y + zm.y), 0.5f * (zm.x - zk.x));
            size_t off = ((size_t)(b * 257 + k) << 9) + (size_t)(g * 8 + 2 * p);
            H2X2 val;
            val.e = __float22half2_rn(Xe);
            val.o = __float22half2_rn(Xo);
            *reinterpret_cast<H2X2*>(&g_scratch[off]) = val;
        }
    }
}

// Kernel 2: column FFT for k = 0..256, masked magnitude sums (interior k x2),
// finalize fused via last-block reduction.
__global__ void __launch_bounds__(NTHR) fft_cols_kernel(float* __restrict__ out){
    __shared__ float2 sbuf[4 * REG_PITCH];
    __shared__ float redL[8], redT[8];
    __shared__ int   is_last;
    __shared__ float sc[32];
    const int tid = threadIdx.x;
    const int b   = blockIdx.x / 65;
    const int kg  = blockIdx.x % 65;
    const int rr  = tid >> 6;
    const int n   = tid & 63;
    const int krow  = kg * 4 + rr;
    const bool valid = (krow < 257);

    const __half2* src = g_scratch + ((size_t)(b * 257 + (valid ? krow : 0)) << 9);
    float2 a[8];
    #pragma unroll
    for (int m = 0; m < 8; m++){
        __half2 h = __ldcs(src + n + 64 * m);
        float2 v = __half22float2(h);
        a[m] = valid ? v : make_float2(0.0f, 0.0f);
    }

    fft512(a, sbuf + rr * REG_PITCH, n);

    // a[t1] = F[u][krow], u = (n>>3) + 8*(n&7) + 64*t1
    const int ub = (n >> 3) + 8 * (n & 7);
    float wgt = !valid ? 0.0f : ((krow == 0 || krow == 256) ? 1.0f : 2.0f);
    float dx  = (float)(krow - 256);
    float dx2 = dx * dx;
    float L = 0.0f, T = 0.0f;
    #pragma unroll
    for (int t1 = 0; t1 < 8; t1++){
        int u = ub + 64 * t1;
        float2 v = a[t1];
        float mag = fsqrt_approx(v.x * v.x + v.y * v.y);
        T += mag;
        float dy = (float)(u - 256);
        if (dy * dy + dx2 <= 2621.44f) L += mag;   // (512*0.1)^2
    }
    L *= wgt; T *= wgt;

    #pragma unroll
    for (int o = 16; o; o >>= 1){
        L += __shfl_down_sync(0xffffffffu, L, o);
        T += __shfl_down_sync(0xffffffffu, T, o);
    }
    const int wid = tid >> 5, lane = tid & 31;
    if (lane == 0){ redL[wid] = L; redT[wid] = T; }
    __syncthreads();
    if (tid == 0){
        float sl = 0.0f, st = 0.0f;
        #pragma unroll
        for (int q = 0; q < 8; q++){ sl += redL[q]; st += redT[q]; }
        g_plow[blockIdx.x] = sl;
        g_ptot[blockIdx.x] = st;
        __threadfence();                       // publish partials
        unsigned int c = atomicAdd(&g_count, 1u);
        is_last = (c == (unsigned int)(gridDim.x - 1));
    }
    __syncthreads();

    // Last arriving block performs the deterministic final reduction.
    if (is_last){
        __threadfence();                       // acquire all partials
        #pragma unroll
        for (int q = 0; q < 4; q++){
            int im = wid * 4 + q;              // 8 warps x 4 images = 32
            float Ls = 0.0f, Ts = 0.0f;
            for (int j = lane; j < 65; j += 32){
                Ls += g_plow[im * 65 + j];
                Ts += g_ptot[im * 65 + j];
            }
            #pragma unroll
            for (int o = 16; o; o >>= 1){
                Ls += __shfl_down_sync(0xffffffffu, Ls, o);
                Ts += __shfl_down_sync(0xffffffffu, Ts, o);
            }
            if (lane == 0) sc[im] = Ls / Ts;
        }
        __syncthreads();
        if (wid == 0){
            float v = sc[lane];
            #pragma unroll
            for (int o = 16; o; o >>= 1) v += __shfl_down_sync(0xffffffffu, v, o);
            if (lane == 0){
                out[0] = v * (1.0f / 32.0f);
                g_count = 0;                   // reset for graph replay
            }
        }
    }
}

extern "C" void kernel_launch(void* const* d_in, const int* in_sizes, int n_in,
                              void* d_out, int out_size){
    const float* img = (const float*)d_in[0];
    float* out = (float*)d_out;
    (void)in_sizes; (void)n_in; (void)out_size;

    fft_rows_kernel<<<32 * 64, NTHR>>>(img);
    fft_cols_kernel<<<32 * 65, NTHR>>>(out);
}